// round 16
// baseline (speedup 1.0000x reference)
#include <cuda_runtime.h>
#include <cuda_bf16.h>
#include <cstdint>
#include <cstddef>

#define NNODES 50000
#define NEDGES 800000
#define EMBD   96
#define HIDD   192

// ---- scratch (static __device__ arrays; zero-initialized at load) ----
__device__ int   g_counts[NNODES];        // zeroed by scanscatter_k for the next call
__device__ int   g_offsets[NNODES + 1];   // intra-block exclusive prefix (+ sentinel)
__device__ int   g_blocksums[64];         // exclusive block sums
__device__ int   g_rank[NEDGES];          // edge's rank within its dst (from hist)
__device__ int   g_tick;                  // ticket counter (reset by last scan block)
__device__ int   g_bar;                   // grid barrier arrive counter
__device__ int   g_bar2;                  // grid barrier reset counter
__device__ int2  g_csr[NEDGES];           // (src, eid)
__device__ float g_aggr[(size_t)NNODES * EMBD];

// ---------------- kernel 1: histogram + rank ----------------

__global__ void hist_k(const int* __restrict__ dst, int n) {
    int i = blockIdx.x * blockDim.x + threadIdx.x;
    if (i < n) g_rank[i] = atomicAdd(&g_counts[dst[i]], 1);
}

// ---------------- kernel 2: FUSED scan + scatter (persistent, grid barrier) ----------------
// Grid must fit in one wave: 512 blocks x 256 thr, ~1KB smem -> 8 blocks/SM -> capacity 1184 >= 512.
// Phase A: blocks < nsb scan 1024 counts each (+ ticket-fused top scan, zero counts).
// Grid barrier (replay-safe arrive/reset counters).
// Phase B: all blocks grid-stride scatter edges into CSR (no atomics).

#define SS_BLOCKS 512

__global__ void __launch_bounds__(256, 8)
scanscatter_k(const int* __restrict__ src, const int* __restrict__ dst,
              int n, int nedges, int nsb) {
    __shared__ int s[256];
    __shared__ int is_last;
    int tid = threadIdx.x;
    int bid = blockIdx.x;

    // ---- phase A: block scan (only first nsb blocks) ----
    if (bid < nsb) {
        int base = bid * 1024 + tid * 4;
        int excl[4];
        int sum = 0;
#pragma unroll
        for (int i = 0; i < 4; i++) {
            int idx = base + i;
            int c = 0;
            if (idx < n) {
                c = g_counts[idx];
                g_counts[idx] = 0;   // ready for next call's hist
            }
            excl[i] = sum;
            sum += c;
        }
        s[tid] = sum;
        __syncthreads();
        for (int off = 1; off < 256; off <<= 1) {
            int t = (tid >= off) ? s[tid - off] : 0;
            __syncthreads();
            s[tid] += t;
            __syncthreads();
        }
        int texcl = s[tid] - sum;
#pragma unroll
        for (int i = 0; i < 4; i++) {
            int idx = base + i;
            if (idx < n) g_offsets[idx] = texcl + excl[i];
        }
        if (tid == 255) g_blocksums[bid] = s[255];

        // last finished scan block: exclusive-scan the block sums + sentinel
        __threadfence();
        if (tid == 0) {
            int t = atomicAdd(&g_tick, 1);
            is_last = (t == nsb - 1);
        }
        __syncthreads();
        if (is_last) {
            int v = (tid < 64 && tid < nsb) ? g_blocksums[tid] : 0;
            if (tid < 64) s[tid] = v;
            __syncthreads();
            for (int off = 1; off < 64; off <<= 1) {
                int t = (tid >= off && tid < 64) ? s[tid - off] : 0;
                __syncthreads();
                if (tid < 64) s[tid] += t;
                __syncthreads();
            }
            if (tid < nsb) {
                int e = s[tid] - v;          // exclusive prefix
                g_blocksums[tid] = e;
                if (tid == nsb - 1) g_offsets[n] = nedges - e;  // sentinel
            }
            __syncthreads();
            if (tid == 0) g_tick = 0;        // ready for next call
        }
    }

    // ---- grid barrier ----
    __syncthreads();
    if (tid == 0) {
        __threadfence();
        atomicAdd(&g_bar, 1);
        while (*(volatile int*)&g_bar < SS_BLOCKS) { }
    }
    __syncthreads();

    // ---- phase B: scatter (grid-stride, cross-SM reads bypass L1 via __ldcg) ----
    for (int i = bid * 256 + tid; i < nedges; i += SS_BLOCKS * 256) {
        int d   = dst[i];
        int pos = __ldcg(&g_offsets[d]) + __ldcg(&g_blocksums[d >> 10]) + g_rank[i];
        g_csr[pos] = make_int2(src[i], i);
    }

    // ---- replay-safe barrier reset (last block to finish resets both counters) ----
    __syncthreads();
    if (tid == 0) {
        int t2 = atomicAdd(&g_bar2, 1);
        if (t2 == SS_BLOCKS - 1) { g_bar = 0; g_bar2 = 0; }
    }
}

// ---------------- kernel 3: aggregation (R13 scalar — best known) ----------------

__global__ void aggregate_k(const float* __restrict__ h, const float* __restrict__ ea, int nnodes) {
    int gw   = (blockIdx.x * blockDim.x + threadIdx.x) >> 5;
    int lane = threadIdx.x & 31;
    if (gw >= nnodes) return;
    int beg = g_offsets[gw]     + g_blocksums[gw >> 10];
    int end = g_offsets[gw + 1] + g_blocksums[(gw + 1) >> 10];
    float a0 = 0.f, a1 = 0.f, a2 = 0.f;
    for (int i = beg; i < end; i++) {
        int2 c = g_csr[i];
        const float* ep = ea + (size_t)c.y * EMBD;
        const float* hp = h  + (size_t)c.x * EMBD;
        a0 += __ldcs(ep + lane)      + hp[lane];
        a1 += __ldcs(ep + lane + 32) + hp[lane + 32];
        a2 += __ldcs(ep + lane + 64) + hp[lane + 64];
    }
    float* op = g_aggr + (size_t)gw * EMBD;
    op[lane]      = a0;
    op[lane + 32] = a1;
    op[lane + 64] = a2;
}

// ---------------- kernel 4: tensor-core MLP (R5-identical) ----------------
// Per CTA: 128 nodes, 512 threads (16 warps).
// GEMM1: aggr[128x96] @ W1[96x192], relu+b1 -> GEMM2: hidden[128x192] @ W2[192x96] + b2 + (1+eps)*h.
// bf16 hi/lo 3-pass split (AhBh + AhBl + AlBh); f32 accumulate.

#define MT 128
#define THREADS_MLP 512

// Padded pitches (bytes): P1/4 mod 32 = 20, P2/4 mod 32 = 4 -> conflict-free frag rows.
#define P1 208
#define P2 400

#define O_A1H 0
#define O_A1L (O_A1H + 128 * P1)
#define O_B1H (O_A1L + 128 * P1)
#define O_B1L (O_B1H + 192 * P1)
#define O_A2H 0
#define O_A2L (O_A2H + 128 * P2)
#define O_B2H (O_A2L + 128 * P2)
#define O_B2L (O_B2H + 96 * P2)
#define O_B1S 179200
#define O_B2S (O_B1S + 768)
#define SMEM_MLP (O_B2S + 384)

__device__ __forceinline__ void mma16816(float* c, const uint32_t* a, const uint32_t* b) {
    asm volatile("mma.sync.aligned.m16n8k16.row.col.f32.bf16.bf16.f32 "
                 "{%0,%1,%2,%3}, {%4,%5,%6,%7}, {%8,%9}, {%0,%1,%2,%3};"
                 : "+f"(c[0]), "+f"(c[1]), "+f"(c[2]), "+f"(c[3])
                 : "r"(a[0]), "r"(a[1]), "r"(a[2]), "r"(a[3]), "r"(b[0]), "r"(b[1]));
}

__device__ __forceinline__ void cvt_hilo(float x, unsigned short& hi, unsigned short& lo) {
    __nv_bfloat16 bh = __float2bfloat16(x);
    __nv_bfloat16 bl = __float2bfloat16(x - __bfloat162float(bh));
    hi = __bfloat16_as_ushort(bh);
    lo = __bfloat16_as_ushort(bl);
}

__device__ __forceinline__ uint32_t pack2(unsigned short a, unsigned short b) {
    return (uint32_t)a | ((uint32_t)b << 16);
}

__global__ void __launch_bounds__(THREADS_MLP, 1)
mlp_mma_k(const float* __restrict__ h,
          const float* __restrict__ W1, const float* __restrict__ b1,
          const float* __restrict__ W2, const float* __restrict__ b2,
          const float* __restrict__ eps,
          float* __restrict__ out, int nnodes)
{
    extern __shared__ char sm[];
    int tid  = threadIdx.x;
    int wid  = tid >> 5;
    int lane = tid & 31;
    int node0 = blockIdx.x * MT;

    if (tid < HIDD) ((float*)(sm + O_B1S))[tid] = b1[tid];
    if (tid < EMBD) ((float*)(sm + O_B2S))[tid] = b2[tid];

    // B1 = W1^T as [n=192 rows][k=96 cols], hi/lo bf16
    for (int i = tid; i < EMBD * HIDD; i += THREADS_MLP) {
        int k = i / HIDD, n = i % HIDD;
        unsigned short hh, ll;
        cvt_hilo(W1[i], hh, ll);
        *(unsigned short*)(sm + O_B1H + n * P1 + k * 2) = hh;
        *(unsigned short*)(sm + O_B1L + n * P1 + k * 2) = ll;
    }
    // A1 = aggr tile [m=128 rows][k=96 cols], hi/lo bf16 packed pairs
    int remain = nnodes - node0; if (remain > MT) remain = MT;
    for (int i = tid; i < remain * (EMBD / 2); i += THREADS_MLP) {
        int m = i / (EMBD / 2), c2 = (i % (EMBD / 2)) * 2;
        float2 v = *(const float2*)(g_aggr + (size_t)(node0 + m) * EMBD + c2);
        unsigned short h0, l0, h1, l1;
        cvt_hilo(v.x, h0, l0);
        cvt_hilo(v.y, h1, l1);
        *(uint32_t*)(sm + O_A1H + m * P1 + c2 * 2) = pack2(h0, h1);
        *(uint32_t*)(sm + O_A1L + m * P1 + c2 * 2) = pack2(l0, l1);
    }
    __syncthreads();

    int wm = wid & 3;
    int wn = wid >> 2;
    int rq = lane >> 2;
    int kq = (lane & 3) * 2;

    // ---- GEMM1: warp tile 32x48, K=96, 3 passes ----
    float c1[2][6][4];
#pragma unroll
    for (int mf = 0; mf < 2; mf++)
#pragma unroll
        for (int nf = 0; nf < 6; nf++)
#pragma unroll
            for (int q = 0; q < 4; q++) c1[mf][nf][q] = 0.f;

    for (int ks = 0; ks < 6; ks++) {
        int k0 = ks * 16 + kq;
        uint32_t ah[2][4], al[2][4];
#pragma unroll
        for (int mf = 0; mf < 2; mf++) {
            int r = wm * 32 + mf * 16 + rq;
            ah[mf][0] = *(const uint32_t*)(sm + O_A1H + r * P1 + k0 * 2);
            ah[mf][1] = *(const uint32_t*)(sm + O_A1H + (r + 8) * P1 + k0 * 2);
            ah[mf][2] = *(const uint32_t*)(sm + O_A1H + r * P1 + (k0 + 8) * 2);
            ah[mf][3] = *(const uint32_t*)(sm + O_A1H + (r + 8) * P1 + (k0 + 8) * 2);
            al[mf][0] = *(const uint32_t*)(sm + O_A1L + r * P1 + k0 * 2);
            al[mf][1] = *(const uint32_t*)(sm + O_A1L + (r + 8) * P1 + k0 * 2);
            al[mf][2] = *(const uint32_t*)(sm + O_A1L + r * P1 + (k0 + 8) * 2);
            al[mf][3] = *(const uint32_t*)(sm + O_A1L + (r + 8) * P1 + (k0 + 8) * 2);
        }
#pragma unroll
        for (int nf = 0; nf < 6; nf++) {
            int n = wn * 48 + nf * 8 + rq;
            uint32_t bh[2], bl[2];
            bh[0] = *(const uint32_t*)(sm + O_B1H + n * P1 + k0 * 2);
            bh[1] = *(const uint32_t*)(sm + O_B1H + n * P1 + (k0 + 8) * 2);
            bl[0] = *(const uint32_t*)(sm + O_B1L + n * P1 + k0 * 2);
            bl[1] = *(const uint32_t*)(sm + O_B1L + n * P1 + (k0 + 8) * 2);
#pragma unroll
            for (int mf = 0; mf < 2; mf++) {
                mma16816(c1[mf][nf], ah[mf], bh);
                mma16816(c1[mf][nf], ah[mf], bl);
                mma16816(c1[mf][nf], al[mf], bh);
            }
        }
    }
    __syncthreads();

    // ---- epilogue1: hidden = relu(c1 + b1) -> A2 hi/lo ----
    {
        const float* b1s = (const float*)(sm + O_B1S);
#pragma unroll
        for (int mf = 0; mf < 2; mf++) {
            int r = wm * 32 + mf * 16 + rq;
#pragma unroll
            for (int nf = 0; nf < 6; nf++) {
                int n0 = wn * 48 + nf * 8 + kq;
                float bb0 = b1s[n0], bb1 = b1s[n0 + 1];
                float v0 = fmaxf(c1[mf][nf][0] + bb0, 0.f);
                float v1 = fmaxf(c1[mf][nf][1] + bb1, 0.f);
                float v2 = fmaxf(c1[mf][nf][2] + bb0, 0.f);
                float v3 = fmaxf(c1[mf][nf][3] + bb1, 0.f);
                unsigned short h0, l0, h1, l1;
                cvt_hilo(v0, h0, l0); cvt_hilo(v1, h1, l1);
                *(uint32_t*)(sm + O_A2H + r * P2 + n0 * 2) = pack2(h0, h1);
                *(uint32_t*)(sm + O_A2L + r * P2 + n0 * 2) = pack2(l0, l1);
                cvt_hilo(v2, h0, l0); cvt_hilo(v3, h1, l1);
                *(uint32_t*)(sm + O_A2H + (r + 8) * P2 + n0 * 2) = pack2(h0, h1);
                *(uint32_t*)(sm + O_A2L + (r + 8) * P2 + n0 * 2) = pack2(l0, l1);
            }
        }
    }
    // B2 = W2^T as [n=96 rows][k=192 cols]
    for (int i = tid; i < HIDD * EMBD; i += THREADS_MLP) {
        int k = i / EMBD, n = i % EMBD;
        unsigned short hh, ll;
        cvt_hilo(W2[i], hh, ll);
        *(unsigned short*)(sm + O_B2H + n * P2 + k * 2) = hh;
        *(unsigned short*)(sm + O_B2L + n * P2 + k * 2) = ll;
    }
    __syncthreads();

    // ---- GEMM2: warp tile 32x24, K=192, 3 passes ----
    float c2a[2][3][4];
#pragma unroll
    for (int mf = 0; mf < 2; mf++)
#pragma unroll
        for (int nf = 0; nf < 3; nf++)
#pragma unroll
            for (int q = 0; q < 4; q++) c2a[mf][nf][q] = 0.f;

    for (int ks = 0; ks < 12; ks++) {
        int k0 = ks * 16 + kq;
        uint32_t ah[2][4], al[2][4];
#pragma unroll
        for (int mf = 0; mf < 2; mf++) {
            int r = wm * 32 + mf * 16 + rq;
            ah[mf][0] = *(const uint32_t*)(sm + O_A2H + r * P2 + k0 * 2);
            ah[mf][1] = *(const uint32_t*)(sm + O_A2H + (r + 8) * P2 + k0 * 2);
            ah[mf][2] = *(const uint32_t*)(sm + O_A2H + r * P2 + (k0 + 8) * 2);
            ah[mf][3] = *(const uint32_t*)(sm + O_A2H + (r + 8) * P2 + (k0 + 8) * 2);
            al[mf][0] = *(const uint32_t*)(sm + O_A2L + r * P2 + k0 * 2);
            al[mf][1] = *(const uint32_t*)(sm + O_A2L + (r + 8) * P2 + k0 * 2);
            al[mf][2] = *(const uint32_t*)(sm + O_A2L + r * P2 + (k0 + 8) * 2);
            al[mf][3] = *(const uint32_t*)(sm + O_A2L + (r + 8) * P2 + (k0 + 8) * 2);
        }
#pragma unroll
        for (int nf = 0; nf < 3; nf++) {
            int n = wn * 24 + nf * 8 + rq;
            uint32_t bh[2], bl[2];
            bh[0] = *(const uint32_t*)(sm + O_B2H + n * P2 + k0 * 2);
            bh[1] = *(const uint32_t*)(sm + O_B2H + n * P2 + (k0 + 8) * 2);
            bl[0] = *(const uint32_t*)(sm + O_B2L + n * P2 + k0 * 2);
            bl[1] = *(const uint32_t*)(sm + O_B2L + n * P2 + (k0 + 8) * 2);
#pragma unroll
            for (int mf = 0; mf < 2; mf++) {
                mma16816(c2a[mf][nf], ah[mf], bh);
                mma16816(c2a[mf][nf], ah[mf], bl);
                mma16816(c2a[mf][nf], al[mf], bh);
            }
        }
    }

    // ---- epilogue2: out = (1+eps)*h + c2 + b2 ----
    {
        float scale = 1.0f + eps[0];
        const float* b2s = (const float*)(sm + O_B2S);
#pragma unroll
        for (int mf = 0; mf < 2; mf++) {
            int r = wm * 32 + mf * 16 + rq;
#pragma unroll
            for (int nf = 0; nf < 3; nf++) {
                int n0 = wn * 24 + nf * 8 + kq;
                float bb0 = b2s[n0], bb1 = b2s[n0 + 1];
                int nodeA = node0 + r;
                if (nodeA < nnodes) {
                    float2 hv = *(const float2*)(h + (size_t)nodeA * EMBD + n0);
                    float2 o;
                    o.x = fmaf(scale, hv.x, c2a[mf][nf][0] + bb0);
                    o.y = fmaf(scale, hv.y, c2a[mf][nf][1] + bb1);
                    *(float2*)(out + (size_t)nodeA * EMBD + n0) = o;
                }
                int nodeB = nodeA + 8;
                if (nodeB < nnodes) {
                    float2 hv = *(const float2*)(h + (size_t)nodeB * EMBD + n0);
                    float2 o;
                    o.x = fmaf(scale, hv.x, c2a[mf][nf][2] + bb0);
                    o.y = fmaf(scale, hv.y, c2a[mf][nf][3] + bb1);
                    *(float2*)(out + (size_t)nodeB * EMBD + n0) = o;
                }
            }
        }
    }
}

// ---------------- launch ----------------

extern "C" void kernel_launch(void* const* d_in, const int* in_sizes, int n_in,
                              void* d_out, int out_size) {
    const float* h   = (const float*)d_in[0];
    const float* ea  = (const float*)d_in[1];
    const int*   src = (const int*)d_in[2];
    const int*   dst = (const int*)d_in[3];
    const float* W1  = (const float*)d_in[4];
    const float* b1  = (const float*)d_in[5];
    const float* W2  = (const float*)d_in[6];
    const float* b2  = (const float*)d_in[7];
    const float* eps = (const float*)d_in[8];
    float* out = (float*)d_out;

    int E = in_sizes[2];
    int N = in_sizes[0] / EMBD;

    hist_k<<<(E + 255) / 256, 256>>>(dst, E);
    int nsb = (N + 1023) / 1024;
    scanscatter_k<<<SS_BLOCKS, 256>>>(src, dst, N, E, nsb);
    aggregate_k<<<(N * 32 + 255) / 256, 256>>>(h, ea, N);

    cudaFuncSetAttribute(mlp_mma_k, cudaFuncAttributeMaxDynamicSharedMemorySize, SMEM_MLP);
    mlp_mma_k<<<(N + MT - 1) / MT, THREADS_MLP, SMEM_MLP>>>(h, W1, b1, W2, b2, eps, out, N);
}

// round 17
// speedup vs baseline: 1.0622x; 1.0622x over previous
#include <cuda_runtime.h>
#include <cuda_bf16.h>
#include <cstdint>
#include <cstddef>

#define NNODES 50000
#define NEDGES 800000
#define EMBD   96
#define HIDD   192

// ---- scratch (static __device__ arrays; zero-initialized at load) ----
__device__ int   g_counts[NNODES];        // zeroed by scan_block_k for the next call
__device__ int   g_offsets[NNODES + 1];   // intra-block exclusive prefix (+ sentinel)
__device__ int   g_blocksums[64];         // exclusive block sums
__device__ int   g_rank[NEDGES];          // edge's rank within its dst (from hist)
__device__ int   g_tick;                  // ticket counter (reset by last block)
__device__ int2  g_csr[NEDGES];           // (src, eid)
__device__ float g_aggr[(size_t)NNODES * EMBD];

// ---------------- kernel 1: histogram + rank ----------------

__global__ void hist_k(const int* __restrict__ dst, int n) {
    int i = blockIdx.x * blockDim.x + threadIdx.x;
    if (i < n) g_rank[i] = atomicAdd(&g_counts[dst[i]], 1);
}

// ---------------- kernel 2: block scan + zero counts + ticket-fused top scan ----------------

__global__ void scan_block_k(int n, int nblocks, int nedges) {
    __shared__ int s[256];
    __shared__ int is_last;
    int tid  = threadIdx.x;
    int base = blockIdx.x * 1024 + tid * 4;
    int excl[4];
    int sum = 0;
#pragma unroll
    for (int i = 0; i < 4; i++) {
        int idx = base + i;
        int c = 0;
        if (idx < n) {
            c = g_counts[idx];
            g_counts[idx] = 0;   // ready for next call's hist
        }
        excl[i] = sum;
        sum += c;
    }
    s[tid] = sum;
    __syncthreads();
    for (int off = 1; off < 256; off <<= 1) {
        int t = (tid >= off) ? s[tid - off] : 0;
        __syncthreads();
        s[tid] += t;
        __syncthreads();
    }
    int texcl = s[tid] - sum;
#pragma unroll
    for (int i = 0; i < 4; i++) {
        int idx = base + i;
        if (idx < n) g_offsets[idx] = texcl + excl[i];
    }
    if (tid == 255) g_blocksums[blockIdx.x] = s[255];

    // last finished block: exclusive-scan the block sums + write sentinel
    __threadfence();
    if (tid == 0) {
        int t = atomicAdd(&g_tick, 1);
        is_last = (t == nblocks - 1);
    }
    __syncthreads();
    if (is_last) {
        int v = (tid < 64 && tid < nblocks) ? g_blocksums[tid] : 0;
        if (tid < 64) s[tid] = v;
        __syncthreads();
        for (int off = 1; off < 64; off <<= 1) {
            int t = (tid >= off && tid < 64) ? s[tid - off] : 0;
            __syncthreads();
            if (tid < 64) s[tid] += t;
            __syncthreads();
        }
        if (tid < nblocks) {
            int e = s[tid] - v;          // exclusive prefix
            g_blocksums[tid] = e;
            // sentinel: offsets[n] + blocksums[n>>10] == nedges
            if (tid == nblocks - 1) g_offsets[n] = nedges - e;
        }
        __syncthreads();
        if (tid == 0) g_tick = 0;        // ready for next call
    }
}

// ---------------- kernel 3: scatter (no atomics, one STG.64) ----------------

__global__ void scatter_k(const int* __restrict__ src, const int* __restrict__ dst, int n) {
    int i = blockIdx.x * blockDim.x + threadIdx.x;
    if (i < n) {
        int d   = dst[i];
        int pos = g_offsets[d] + g_blocksums[d >> 10] + g_rank[i];
        g_csr[pos] = make_int2(src[i], i);
    }
}

// ---------------- kernel 4: aggregation (R13 scalar — best known) ----------------

__global__ void aggregate_k(const float* __restrict__ h, const float* __restrict__ ea, int nnodes) {
    int gw   = (blockIdx.x * blockDim.x + threadIdx.x) >> 5;
    int lane = threadIdx.x & 31;
    if (gw >= nnodes) return;
    int beg = g_offsets[gw]     + g_blocksums[gw >> 10];
    int end = g_offsets[gw + 1] + g_blocksums[(gw + 1) >> 10];
    float a0 = 0.f, a1 = 0.f, a2 = 0.f;
    for (int i = beg; i < end; i++) {
        int2 c = g_csr[i];
        const float* ep = ea + (size_t)c.y * EMBD;
        const float* hp = h  + (size_t)c.x * EMBD;
        a0 += __ldcs(ep + lane)      + hp[lane];
        a1 += __ldcs(ep + lane + 32) + hp[lane + 32];
        a2 += __ldcs(ep + lane + 64) + hp[lane + 64];
    }
    float* op = g_aggr + (size_t)gw * EMBD;
    op[lane]      = a0;
    op[lane + 32] = a1;
    op[lane + 64] = a2;
}

// ---------------- kernel 5: tensor-core MLP with ldmatrix fragment loads ----------------
// Per CTA: 128 nodes, 512 threads (16 warps).
// GEMM1: aggr[128x96] @ W1[96x192], relu+b1 -> GEMM2: hidden[128x192] @ W2[192x96] + b2 + (1+eps)*h.
// bf16 hi/lo 3-pass split (AhBh + AhBl + AlBh); f32 accumulate.

#define MT 128
#define THREADS_MLP 512

// Padded pitches (bytes): P1/16=13 (odd), P2/16=25 (odd) -> LDSM 8-row fetches conflict-free.
#define P1 208
#define P2 400

#define O_A1H 0
#define O_A1L (O_A1H + 128 * P1)
#define O_B1H (O_A1L + 128 * P1)
#define O_B1L (O_B1H + 192 * P1)
#define O_A2H 0
#define O_A2L (O_A2H + 128 * P2)
#define O_B2H (O_A2L + 128 * P2)
#define O_B2L (O_B2H + 96 * P2)
#define O_B1S 179200
#define O_B2S (O_B1S + 768)
#define SMEM_MLP (O_B2S + 384)

__device__ __forceinline__ uint32_t smem_u32(const void* p) {
    uint32_t a;
    asm("{ .reg .u64 t; cvta.to.shared.u64 t, %1; cvt.u32.u64 %0, t; }" : "=r"(a) : "l"(p));
    return a;
}

__device__ __forceinline__ void ldsm4(uint32_t* r, uint32_t a) {
    asm volatile("ldmatrix.sync.aligned.m8n8.x4.shared.b16 {%0,%1,%2,%3}, [%4];"
                 : "=r"(r[0]), "=r"(r[1]), "=r"(r[2]), "=r"(r[3]) : "r"(a));
}
__device__ __forceinline__ void ldsm2(uint32_t* r, uint32_t a) {
    asm volatile("ldmatrix.sync.aligned.m8n8.x2.shared.b16 {%0,%1}, [%2];"
                 : "=r"(r[0]), "=r"(r[1]) : "r"(a));
}

__device__ __forceinline__ void mma16816(float* c, const uint32_t* a, const uint32_t* b) {
    asm volatile("mma.sync.aligned.m16n8k16.row.col.f32.bf16.bf16.f32 "
                 "{%0,%1,%2,%3}, {%4,%5,%6,%7}, {%8,%9}, {%0,%1,%2,%3};"
                 : "+f"(c[0]), "+f"(c[1]), "+f"(c[2]), "+f"(c[3])
                 : "r"(a[0]), "r"(a[1]), "r"(a[2]), "r"(a[3]), "r"(b[0]), "r"(b[1]));
}

__device__ __forceinline__ void cvt_hilo(float x, unsigned short& hi, unsigned short& lo) {
    __nv_bfloat16 bh = __float2bfloat16(x);
    __nv_bfloat16 bl = __float2bfloat16(x - __bfloat162float(bh));
    hi = __bfloat16_as_ushort(bh);
    lo = __bfloat16_as_ushort(bl);
}

__device__ __forceinline__ uint32_t pack2(unsigned short a, unsigned short b) {
    return (uint32_t)a | ((uint32_t)b << 16);
}

__global__ void __launch_bounds__(THREADS_MLP, 1)
mlp_mma_k(const float* __restrict__ h,
          const float* __restrict__ W1, const float* __restrict__ b1,
          const float* __restrict__ W2, const float* __restrict__ b2,
          const float* __restrict__ eps,
          float* __restrict__ out, int nnodes)
{
    extern __shared__ char sm[];
    int tid  = threadIdx.x;
    int wid  = tid >> 5;
    int lane = tid & 31;
    int node0 = blockIdx.x * MT;

    if (tid < HIDD) ((float*)(sm + O_B1S))[tid] = b1[tid];
    if (tid < EMBD) ((float*)(sm + O_B2S))[tid] = b2[tid];

    // B1 = W1^T as [n=192 rows][k=96 cols], hi/lo bf16
    for (int i = tid; i < EMBD * HIDD; i += THREADS_MLP) {
        int k = i / HIDD, n = i % HIDD;
        unsigned short hh, ll;
        cvt_hilo(W1[i], hh, ll);
        *(unsigned short*)(sm + O_B1H + n * P1 + k * 2) = hh;
        *(unsigned short*)(sm + O_B1L + n * P1 + k * 2) = ll;
    }
    // A1 = aggr tile [m=128 rows][k=96 cols], hi/lo bf16 packed pairs
    int remain = nnodes - node0; if (remain > MT) remain = MT;
    for (int i = tid; i < remain * (EMBD / 2); i += THREADS_MLP) {
        int m = i / (EMBD / 2), c2 = (i % (EMBD / 2)) * 2;
        float2 v = *(const float2*)(g_aggr + (size_t)(node0 + m) * EMBD + c2);
        unsigned short h0, l0, h1, l1;
        cvt_hilo(v.x, h0, l0);
        cvt_hilo(v.y, h1, l1);
        *(uint32_t*)(sm + O_A1H + m * P1 + c2 * 2) = pack2(h0, h1);
        *(uint32_t*)(sm + O_A1L + m * P1 + c2 * 2) = pack2(l0, l1);
    }
    __syncthreads();

    int wm = wid & 3;   // M group: rows [wm*32, +32)
    int wn = wid >> 2;  // N group
    int rq = lane >> 2;
    int kq = (lane & 3) * 2;

    uint32_t smb = smem_u32(sm);
    // ldmatrix lane->address mapping
    // A x4: m0..m3 = (rows 0-8, k0-8) (rows 8-16, k0-8) (rows 0-8, k8-16) (rows 8-16, k8-16)
    int aRow  = lane & 15;
    int aColB = (lane >> 4) * 16;           // 8 cols * 2B
    // B x4: m0..m3 = (nf, k0-8) (nf, k8-16) (nf+1, k0-8) (nf+1, k8-16)
    int bRow  = (lane & 7) + ((lane >> 4) << 3);
    int bColB = ((lane >> 3) & 1) * 16;

    // ---- GEMM1: warp tile 32x48, K=96, 3 passes ----
    uint32_t a1Hb = smb + O_A1H + (wm * 32 + aRow) * P1 + aColB;
    uint32_t a1Lb = a1Hb + (O_A1L - O_A1H);
    uint32_t b1Hb = smb + O_B1H + (wn * 48 + bRow) * P1 + bColB;
    uint32_t b1Lb = b1Hb + (O_B1L - O_B1H);

    float c1[2][6][4];
#pragma unroll
    for (int mf = 0; mf < 2; mf++)
#pragma unroll
        for (int nf = 0; nf < 6; nf++)
#pragma unroll
            for (int q = 0; q < 4; q++) c1[mf][nf][q] = 0.f;

#pragma unroll
    for (int ks = 0; ks < 6; ks++) {
        uint32_t ah[2][4], al[2][4];
        ldsm4(ah[0], a1Hb + ks * 32);
        ldsm4(ah[1], a1Hb + 16 * P1 + ks * 32);
        ldsm4(al[0], a1Lb + ks * 32);
        ldsm4(al[1], a1Lb + 16 * P1 + ks * 32);
#pragma unroll
        for (int p = 0; p < 3; p++) {
            uint32_t bh[4], bl[4];
            ldsm4(bh, b1Hb + p * 16 * P1 + ks * 32);
            ldsm4(bl, b1Lb + p * 16 * P1 + ks * 32);
#pragma unroll
            for (int hf = 0; hf < 2; hf++) {
                int nf = 2 * p + hf;
#pragma unroll
                for (int mf = 0; mf < 2; mf++) {
                    mma16816(c1[mf][nf], ah[mf], bh + 2 * hf);
                    mma16816(c1[mf][nf], ah[mf], bl + 2 * hf);
                    mma16816(c1[mf][nf], al[mf], bh + 2 * hf);
                }
            }
        }
    }
    __syncthreads();

    // ---- epilogue1: hidden = relu(c1 + b1) -> A2 hi/lo ----
    {
        const float* b1s = (const float*)(sm + O_B1S);
#pragma unroll
        for (int mf = 0; mf < 2; mf++) {
            int r = wm * 32 + mf * 16 + rq;
#pragma unroll
            for (int nf = 0; nf < 6; nf++) {
                int n0 = wn * 48 + nf * 8 + kq;
                float bb0 = b1s[n0], bb1 = b1s[n0 + 1];
                float v0 = fmaxf(c1[mf][nf][0] + bb0, 0.f);
                float v1 = fmaxf(c1[mf][nf][1] + bb1, 0.f);
                float v2 = fmaxf(c1[mf][nf][2] + bb0, 0.f);
                float v3 = fmaxf(c1[mf][nf][3] + bb1, 0.f);
                unsigned short h0, l0, h1, l1;
                cvt_hilo(v0, h0, l0); cvt_hilo(v1, h1, l1);
                *(uint32_t*)(sm + O_A2H + r * P2 + n0 * 2) = pack2(h0, h1);
                *(uint32_t*)(sm + O_A2L + r * P2 + n0 * 2) = pack2(l0, l1);
                cvt_hilo(v2, h0, l0); cvt_hilo(v3, h1, l1);
                *(uint32_t*)(sm + O_A2H + (r + 8) * P2 + n0 * 2) = pack2(h0, h1);
                *(uint32_t*)(sm + O_A2L + (r + 8) * P2 + n0 * 2) = pack2(l0, l1);
            }
        }
    }
    // B2 = W2^T as [n=96 rows][k=192 cols]
    for (int i = tid; i < HIDD * EMBD; i += THREADS_MLP) {
        int k = i / EMBD, n = i % EMBD;
        unsigned short hh, ll;
        cvt_hilo(W2[i], hh, ll);
        *(unsigned short*)(sm + O_B2H + n * P2 + k * 2) = hh;
        *(unsigned short*)(sm + O_B2L + n * P2 + k * 2) = ll;
    }
    __syncthreads();

    // ---- GEMM2: warp tile 32x24, K=192, 3 passes ----
    uint32_t a2Hb = smb + O_A2H + (wm * 32 + aRow) * P2 + aColB;
    uint32_t a2Lb = a2Hb + (O_A2L - O_A2H);
    uint32_t b2Hb = smb + O_B2H + (wn * 24 + bRow) * P2 + bColB;
    uint32_t b2Lb = b2Hb + (O_B2L - O_B2H);

    float c2a[2][3][4];
#pragma unroll
    for (int mf = 0; mf < 2; mf++)
#pragma unroll
        for (int nf = 0; nf < 3; nf++)
#pragma unroll
            for (int q = 0; q < 4; q++) c2a[mf][nf][q] = 0.f;

#pragma unroll
    for (int ks = 0; ks < 12; ks++) {
        uint32_t ah[2][4], al[2][4];
        ldsm4(ah[0], a2Hb + ks * 32);
        ldsm4(ah[1], a2Hb + 16 * P2 + ks * 32);
        ldsm4(al[0], a2Lb + ks * 32);
        ldsm4(al[1], a2Lb + 16 * P2 + ks * 32);

        uint32_t bh[4], bl[4], bh2[2], bl2[2];
        ldsm4(bh, b2Hb + ks * 32);             // nf0, nf1
        ldsm4(bl, b2Lb + ks * 32);
        ldsm2(bh2, b2Hb + 16 * P2 + ks * 32);  // nf2 (lanes 0-15 addresses)
        ldsm2(bl2, b2Lb + 16 * P2 + ks * 32);

#pragma unroll
        for (int hf = 0; hf < 2; hf++) {
#pragma unroll
            for (int mf = 0; mf < 2; mf++) {
                mma16816(c2a[mf][hf], ah[mf], bh + 2 * hf);
                mma16816(c2a[mf][hf], ah[mf], bl + 2 * hf);
                mma16816(c2a[mf][hf], al[mf], bh + 2 * hf);
            }
        }
#pragma unroll
        for (int mf = 0; mf < 2; mf++) {
            mma16816(c2a[mf][2], ah[mf], bh2);
            mma16816(c2a[mf][2], ah[mf], bl2);
            mma16816(c2a[mf][2], al[mf], bh2);
        }
    }

    // ---- epilogue2: out = (1+eps)*h + c2 + b2 ----
    {
        float scale = 1.0f + eps[0];
        const float* b2s = (const float*)(sm + O_B2S);
#pragma unroll
        for (int mf = 0; mf < 2; mf++) {
            int r = wm * 32 + mf * 16 + rq;
#pragma unroll
            for (int nf = 0; nf < 3; nf++) {
                int n0 = wn * 24 + nf * 8 + kq;
                float bb0 = b2s[n0], bb1 = b2s[n0 + 1];
                int nodeA = node0 + r;
                if (nodeA < nnodes) {
                    float2 hv = *(const float2*)(h + (size_t)nodeA * EMBD + n0);
                    float2 o;
                    o.x = fmaf(scale, hv.x, c2a[mf][nf][0] + bb0);
                    o.y = fmaf(scale, hv.y, c2a[mf][nf][1] + bb1);
                    *(float2*)(out + (size_t)nodeA * EMBD + n0) = o;
                }
                int nodeB = nodeA + 8;
                if (nodeB < nnodes) {
                    float2 hv = *(const float2*)(h + (size_t)nodeB * EMBD + n0);
                    float2 o;
                    o.x = fmaf(scale, hv.x, c2a[mf][nf][2] + bb0);
                    o.y = fmaf(scale, hv.y, c2a[mf][nf][3] + bb1);
                    *(float2*)(out + (size_t)nodeB * EMBD + n0) = o;
                }
            }
        }
    }
}

// ---------------- launch ----------------

extern "C" void kernel_launch(void* const* d_in, const int* in_sizes, int n_in,
                              void* d_out, int out_size) {
    const float* h   = (const float*)d_in[0];
    const float* ea  = (const float*)d_in[1];
    const int*   src = (const int*)d_in[2];
    const int*   dst = (const int*)d_in[3];
    const float* W1  = (const float*)d_in[4];
    const float* b1  = (const float*)d_in[5];
    const float* W2  = (const float*)d_in[6];
    const float* b2  = (const float*)d_in[7];
    const float* eps = (const float*)d_in[8];
    float* out = (float*)d_out;

    int E = in_sizes[2];
    int N = in_sizes[0] / EMBD;

    hist_k<<<(E + 255) / 256, 256>>>(dst, E);
    int nsb = (N + 1023) / 1024;
    scan_block_k<<<nsb, 256>>>(N, nsb, E);
    scatter_k<<<(E + 255) / 256, 256>>>(src, dst, E);
    aggregate_k<<<(N * 32 + 255) / 256, 256>>>(h, ea, N);

    cudaFuncSetAttribute(mlp_mma_k, cudaFuncAttributeMaxDynamicSharedMemorySize, SMEM_MLP);
    mlp_mma_k<<<(N + MT - 1) / MT, THREADS_MLP, SMEM_MLP>>>(h, W1, b1, W2, b2, eps, out, N);
}